// round 7
// baseline (speedup 1.0000x reference)
#include <cuda_runtime.h>
#include <cstdint>

#define TT 512
#define IDIM 512
#define H 1024
#define G 4096
#define NB 128
#define NT_ENC 256
#define NT_DEC 288

// ---------------- device scratch ----------------
__device__ __align__(16) float d_pre[(size_t)G * TT];       // W_ih_e@x_t + biases   [r][t]
__device__ __align__(16) float d_EH[(size_t)(TT + 1) * H];  // eh_t rows; row0 = 0
__device__ __align__(16) float d_DH[(size_t)(TT + 1) * H];  // dh_t rows; row0 = 0
__device__ unsigned d_fe[NB], d_fd[NB];                     // per-block counters, 8/step

__device__ __forceinline__ float sigf(float x) { return 1.f / (1.f + __expf(-x)); }
__device__ __forceinline__ float dot4(float4 a, float4 b) {
  return a.x * b.x + a.y * b.y + a.z * b.z + a.w * b.w;
}
__device__ __forceinline__ float wredsum(float v) {
#pragma unroll
  for (int o = 16; o; o >>= 1) v += __shfl_xor_sync(0xffffffffu, v, o);
  return v;
}
__device__ __forceinline__ float wredmax(float v) {
#pragma unroll
  for (int o = 16; o; o >>= 1) v = fmaxf(v, __shfl_xor_sync(0xffffffffu, v, o));
  return v;
}
__device__ __forceinline__ unsigned ld_acq(const unsigned* p) {
  unsigned v;
  asm volatile("ld.acquire.gpu.global.u32 %0, [%1];" : "=r"(v) : "l"(p) : "memory");
  return v;
}
__device__ __forceinline__ void red_rel(unsigned* p) {
  unsigned one = 1u;
  asm volatile("red.release.gpu.global.add.u32 [%0], %1;" :: "l"(p), "r"(one) : "memory");
}

// one warp scans 4 counters/lane (128 total) until all >= tgt
__device__ __forceinline__ void poll_flags(const unsigned* flags, int lane, unsigned tgt) {
  const unsigned* fp = flags + lane * 4;
  for (;;) {
    unsigned m0 = ld_acq(fp + 0), m1 = ld_acq(fp + 1);
    unsigned m2 = ld_acq(fp + 2), m3 = ld_acq(fp + 3);
    unsigned m = min(min(m0, m1), min(m2, m3));
    if (__all_sync(0xffffffffu, m >= tgt)) break;
    __nanosleep(32);
  }
}

// ---------------- init ----------------
__global__ void init_state() {
  int i = blockIdx.x * blockDim.x + threadIdx.x;
  if (i < H) { d_EH[i] = 0.f; d_DH[i] = 0.f; }
  if (i < NB) { d_fe[i] = 0u; d_fd[i] = 0u; }
}

// ---------------- R2-proven GEMM: d_pre[r][t] = W_ih_e@x_t + b_ih_e + b_hh_e ----------------
#define BM 64
#define BN 64
#define BK 32
__global__ void __launch_bounds__(256) gemm_pre(const float* __restrict__ A,
                                                const float* __restrict__ B,
                                                const float* __restrict__ bih,
                                                const float* __restrict__ bhh) {
  __shared__ float As[BK][BM + 1];
  __shared__ float Bs[BK][BN + 1];
  int tid = threadIdx.x;
  int r0 = blockIdx.y * BM;
  int t0 = blockIdx.x * BN;
  int tx = tid & 15, ty = tid >> 4;
  float acc[4][4] = {};
  for (int k0 = 0; k0 < IDIM; k0 += BK) {
#pragma unroll
    for (int i = 0; i < 8; ++i) {
      int lin = tid + i * 256;
      int m = lin >> 5, kk = lin & 31;
      As[kk][m] = A[(size_t)(r0 + m) * IDIM + k0 + kk];
      Bs[kk][m] = B[(size_t)(t0 + m) * IDIM + k0 + kk];
    }
    __syncthreads();
#pragma unroll
    for (int kk = 0; kk < BK; ++kk) {
      float a[4], bv[4];
#pragma unroll
      for (int j = 0; j < 4; ++j) { a[j] = As[kk][ty * 4 + j]; bv[j] = Bs[kk][tx * 4 + j]; }
#pragma unroll
      for (int i2 = 0; i2 < 4; ++i2)
#pragma unroll
        for (int j = 0; j < 4; ++j) acc[i2][j] += a[i2] * bv[j];
    }
    __syncthreads();
  }
#pragma unroll
  for (int i2 = 0; i2 < 4; ++i2) {
    int r = r0 + ty * 4 + i2;
    float bias = bih[r] + bhh[r];
#pragma unroll
    for (int j = 0; j < 4; ++j)
      d_pre[(size_t)r * TT + (t0 + tx * 4 + j)] = acc[i2][j] + bias;
  }
}

// ---------------- encoder persistent: warp-autonomous, no intra-block sync ----------------
__global__ void __launch_bounds__(NT_ENC, 1)
enc_persist(const float* __restrict__ Whh_e) {
  const int b = blockIdx.x, tid = threadIdx.x;
  const int w = tid >> 5, lane = tid & 31;
  const int u = b * 8 + w;

  float4 wreg[4][8];
#pragma unroll
  for (int g = 0; g < 4; ++g) {
    const float4* p = (const float4*)(Whh_e + (size_t)(u + g * H) * H);
#pragma unroll
    for (int c = 0; c < 8; ++c) wreg[g][c] = __ldg(p + c * 32 + lane);
  }

  float ec = 0.f;
  for (int t = 0; t < TT; ++t) {
    float pre_g[4];
    if (lane == 0) {
#pragma unroll
      for (int g = 0; g < 4; ++g) pre_g[g] = __ldg(&d_pre[(size_t)(u + g * H) * TT + t]);
    }
    // every warp polls independently — no block coupling
    poll_flags(d_fe, lane, 8u * (unsigned)t);

    // load eh_t straight from L2 into registers
    const float4* src = (const float4*)(d_EH + (size_t)t * H);
    float a[4] = {0.f, 0.f, 0.f, 0.f};
#pragma unroll
    for (int c = 0; c < 8; ++c) {
      float4 hv = __ldcg(src + c * 32 + lane);
#pragma unroll
      for (int g = 0; g < 4; ++g) a[g] += dot4(wreg[g][c], hv);
    }
#pragma unroll
    for (int g = 0; g < 4; ++g) a[g] = wredsum(a[g]);
    if (lane == 0) {
      float gi = a[0] + pre_g[0], gf = a[1] + pre_g[1];
      float gg = a[2] + pre_g[2], go = a[3] + pre_g[3];
      ec = sigf(gf) * ec + sigf(gi) * tanhf(gg);
      __stcg(&d_EH[(size_t)(t + 1) * H + u], sigf(go) * tanhf(ec));
      red_rel(&d_fe[b]);   // per-warp release of its own store
    }
  }
}

// ---------------- decoder persistent ----------------
// smem: shWA [32][1024] = 128KB | shEh 4KB | shDh 4KB | shS
#define SMEM_DEC_FLOATS (32 * 1024 + 1024 + 1024 + 16)

__global__ void __launch_bounds__(NT_DEC, 1)
dec_persist(const float* __restrict__ Wihd, const float* __restrict__ Whhd,
            const float* __restrict__ bihd, const float* __restrict__ bhhd,
            const float* __restrict__ Wattn, const float* __restrict__ battn) {
  extern __shared__ __align__(16) float sh[];
  float* shWA = sh;                  // 32768 floats
  float* shEh = sh + 32 * 1024;      // 1024
  float* shDh = shEh + 1024;         // 1024
  float* shS  = shDh + 1024;         // 16

  const int b = blockIdx.x, tid = threadIdx.x;
  const int w = tid >> 5, lane = tid & 31;
  const int u = b * 8 + w;           // valid for w<8

  // W_A block rows -> smem: row jj = g*8+wv holds Wihd[(b*8+wv)+g*H][0:H]
  for (int i = tid; i < 32 * 256; i += NT_DEC) {
    int jj = i >> 8, c4 = i & 255;
    int g = jj >> 3, wv = jj & 7;
    ((float4*)shWA)[i] =
        __ldg((const float4*)(Wihd + ((size_t)(b * 8 + wv) + (size_t)g * H) * (2 * H)) + c4);
  }

  float4 wreg[4][8];                 // W_ih_d[:,H:] + W_hh_d rows (dh coefficients)
  float bd[4] = {0.f, 0.f, 0.f, 0.f};
  if (w < 8) {
#pragma unroll
    for (int g = 0; g < 4; ++g) {
      const int row = u + g * H;
      const float4* pA = (const float4*)(Wihd + (size_t)row * (2 * H) + H);
      const float4* pB = (const float4*)(Whhd + (size_t)row * H);
#pragma unroll
      for (int c = 0; c < 8; ++c) {
        float4 x = __ldg(pA + c * 32 + lane), y = __ldg(pB + c * 32 + lane);
        wreg[g][c] = make_float4(x.x + y.x, x.y + y.y, x.z + y.z, x.w + y.w);
      }
      bd[g] = __ldg(bihd + row) + __ldg(bhhd + row);
    }
  }
  float awreg[16];                   // warp 8: softmaxed attention weights
#pragma unroll
  for (int j = 0; j < 16; ++j) awreg[j] = 0.f;
  __syncthreads();

  float dc = 0.f;
  for (int t = 0; t < TT; ++t) {
    if (w == 8) poll_flags(d_fd, lane, 8u * (unsigned)t);
    __syncthreads();   // S1: dh_t visible; safe to restage
    if (tid < 256) {
      ((float4*)shEh)[tid] = __ldcg((const float4*)(d_EH + (size_t)(t + 1) * H) + tid);
      ((float4*)shDh)[tid] = __ldcg((const float4*)(d_DH + (size_t)t * H) + tid);
    }
    __syncthreads();   // S2: staged

    float a[4] = {0.f, 0.f, 0.f, 0.f};
    float pa[4] = {0.f, 0.f, 0.f, 0.f};
    if (w < 8) {
#pragma unroll
      for (int c = 0; c < 8; ++c) {
        float4 dhc = ((const float4*)shDh)[c * 32 + lane];
        float4 ehc = ((const float4*)shEh)[c * 32 + lane];
#pragma unroll
        for (int g = 0; g < 4; ++g) {
          a[g]  += dot4(wreg[g][c], dhc);
          pa[g] += dot4(((const float4*)shWA)[(g * 8 + w) * 256 + c * 32 + lane], ehc);
        }
      }
#pragma unroll
      for (int g = 0; g < 4; ++g) { a[g] = wredsum(a[g]); pa[g] = wredsum(pa[g]); }
    } else {
      // full energy + register-resident softmax
      const float4* wrE = (const float4*)(Wattn + (size_t)t * (2 * H));
      const float4* wrD = wrE + 256;   // +H floats
      float e = 0.f;
#pragma unroll
      for (int c = 0; c < 8; ++c) {
        int idx = c * 32 + lane;
        e += dot4(__ldg(wrE + idx), ((const float4*)shEh)[idx]);
        e += dot4(__ldg(wrD + idx), ((const float4*)shDh)[idx]);
      }
      e = wredsum(e) + __ldg(&battn[t]);
      float vals[16];
      float m = -1e30f;
#pragma unroll
      for (int j = 0; j < 16; ++j) {
        float x = (j * 32 + lane == t) ? e : awreg[j];
        vals[j] = x;
        m = fmaxf(m, x);
      }
      m = wredmax(m);
      float ssum = 0.f;
#pragma unroll
      for (int j = 0; j < 16; ++j) { vals[j] = __expf(vals[j] - m); ssum += vals[j]; }
      ssum = wredsum(ssum);
      float inv = 1.f / ssum;
#pragma unroll
      for (int j = 0; j < 16; ++j) awreg[j] = vals[j] * inv;
      if (lane == 0) shS[0] = __expf(e - m) * inv;
    }
    __syncthreads();   // S3: shS published

    if (w < 8 && lane == 0) {
      float s = shS[0];
      float gi = s * pa[0] + a[0] + bd[0];
      float gf = s * pa[1] + a[1] + bd[1];
      float gg = s * pa[2] + a[2] + bd[2];
      float go = s * pa[3] + a[3] + bd[3];
      dc = sigf(gf) * dc + sigf(gi) * tanhf(gg);
      __stcg(&d_DH[(size_t)(t + 1) * H + u], sigf(go) * tanhf(dc));
      red_rel(&d_fd[b]);   // per-warp release of its own store
    }
  }
}

// ---------------- out[t] = Wout @ dh_{t+1} + bout ----------------
__global__ void out_final(const float* __restrict__ Wout, const float* __restrict__ bout,
                          float* __restrict__ out) {
  const int w = threadIdx.x >> 5, lane = threadIdx.x & 31;
  const int t = blockIdx.x * 8 + w;
  const float4* wo = (const float4*)Wout;
  const float4* dh = (const float4*)(d_DH + (size_t)(t + 1) * H);
  float o = 0.f;
#pragma unroll
  for (int c = 0; c < 8; ++c) o += dot4(__ldg(wo + c * 32 + lane), __ldcg(dh + c * 32 + lane));
  o = wredsum(o);
  if (lane == 0) out[t] = o + __ldg(bout);
}

// ---------------- launch ----------------
extern "C" void kernel_launch(void* const* d_in, const int* in_sizes, int n_in,
                              void* d_out, int out_size) {
  const float* input_seq = (const float*)d_in[0];
  const float* W_ih_e = (const float*)d_in[2];
  const float* W_hh_e = (const float*)d_in[3];
  const float* b_ih_e = (const float*)d_in[4];
  const float* b_hh_e = (const float*)d_in[5];
  const float* W_attn = (const float*)d_in[6];
  const float* b_attn = (const float*)d_in[7];
  const float* W_ih_d = (const float*)d_in[8];
  const float* W_hh_d = (const float*)d_in[9];
  const float* b_ih_d = (const float*)d_in[10];
  const float* b_hh_d = (const float*)d_in[11];
  const float* W_out  = (const float*)d_in[12];
  const float* b_out  = (const float*)d_in[13];
  float* out = (float*)d_out;

  const int smem_dec = SMEM_DEC_FLOATS * 4;   // ~139KB
  cudaFuncSetAttribute(dec_persist, cudaFuncAttributeMaxDynamicSharedMemorySize, smem_dec);

  init_state<<<4, 256>>>();
  gemm_pre<<<dim3(TT / BN, G / BM), 256>>>(W_ih_e, input_seq, b_ih_e, b_hh_e);
  enc_persist<<<NB, NT_ENC>>>(W_hh_e);
  dec_persist<<<NB, NT_DEC, smem_dec>>>(W_ih_d, W_hh_d, b_ih_d, b_hh_d, W_attn, b_attn);
  out_final<<<TT / 8, 256>>>(W_out, b_out, out);
}

// round 8
// speedup vs baseline: 1.6369x; 1.6369x over previous
#include <cuda_runtime.h>
#include <cstdint>

#define TT 512
#define IDIM 512
#define H 1024
#define G 4096
#define NB 128
#define NT_ENC 256
#define NT_DEC 288
#define FPAD 32   // flag padding: 32 uints = 128B line per flag

// ---------------- device scratch ----------------
__device__ __align__(16) float d_pre[(size_t)G * TT];       // W_ih_e@x_t + biases   [r][t]
__device__ __align__(16) float d_EH[(size_t)(TT + 1) * H];  // eh_t rows; row0 = 0
__device__ __align__(16) float d_DH[(size_t)(TT + 1) * H];  // dh_t rows; row0 = 0
__device__ unsigned d_fe[NB * FPAD], d_fd[NB * FPAD];       // padded per-block counters, 8/step

__device__ __forceinline__ float sigf(float x) { return 1.f / (1.f + __expf(-x)); }
__device__ __forceinline__ float dot4(float4 a, float4 b) {
  return a.x * b.x + a.y * b.y + a.z * b.z + a.w * b.w;
}
__device__ __forceinline__ float wredsum(float v) {
#pragma unroll
  for (int o = 16; o; o >>= 1) v += __shfl_xor_sync(0xffffffffu, v, o);
  return v;
}
__device__ __forceinline__ float wredmax(float v) {
#pragma unroll
  for (int o = 16; o; o >>= 1) v = fmaxf(v, __shfl_xor_sync(0xffffffffu, v, o));
  return v;
}
__device__ __forceinline__ unsigned ld_acq(const unsigned* p) {
  unsigned v;
  asm volatile("ld.acquire.gpu.global.u32 %0, [%1];" : "=r"(v) : "l"(p) : "memory");
  return v;
}
__device__ __forceinline__ void red_rel(unsigned* p) {
  unsigned one = 1u;
  asm volatile("red.release.gpu.global.add.u32 [%0], %1;" :: "l"(p), "r"(one) : "memory");
}

// one warp scans 4 padded flags/lane (128 blocks) until all >= tgt
__device__ __forceinline__ void poll_flags(const unsigned* flags, int lane, unsigned tgt) {
  for (;;) {
    unsigned a0 = ld_acq(flags + (size_t)lane * FPAD);
    unsigned a1 = ld_acq(flags + (size_t)(lane + 32) * FPAD);
    unsigned a2 = ld_acq(flags + (size_t)(lane + 64) * FPAD);
    unsigned a3 = ld_acq(flags + (size_t)(lane + 96) * FPAD);
    unsigned mn = min(min(a0, a1), min(a2, a3));
    if (__all_sync(0xffffffffu, mn >= tgt)) break;
    __nanosleep(32);
  }
}

// ---------------- init ----------------
__global__ void init_state() {
  int i = blockIdx.x * blockDim.x + threadIdx.x;
  if (i < H) { d_EH[i] = 0.f; d_DH[i] = 0.f; }
  if (i < NB * FPAD) { d_fe[i] = 0u; d_fd[i] = 0u; }
}

// ---------------- R2-proven GEMM: d_pre[r][t] = W_ih_e@x_t + b_ih_e + b_hh_e ----------------
#define BM 64
#define BN 64
#define BK 32
__global__ void __launch_bounds__(256) gemm_pre(const float* __restrict__ A,
                                                const float* __restrict__ B,
                                                const float* __restrict__ bih,
                                                const float* __restrict__ bhh) {
  __shared__ float As[BK][BM + 1];
  __shared__ float Bs[BK][BN + 1];
  int tid = threadIdx.x;
  int r0 = blockIdx.y * BM;
  int t0 = blockIdx.x * BN;
  int tx = tid & 15, ty = tid >> 4;
  float acc[4][4] = {};
  for (int k0 = 0; k0 < IDIM; k0 += BK) {
#pragma unroll
    for (int i = 0; i < 8; ++i) {
      int lin = tid + i * 256;
      int m = lin >> 5, kk = lin & 31;
      As[kk][m] = A[(size_t)(r0 + m) * IDIM + k0 + kk];
      Bs[kk][m] = B[(size_t)(t0 + m) * IDIM + k0 + kk];
    }
    __syncthreads();
#pragma unroll
    for (int kk = 0; kk < BK; ++kk) {
      float a[4], bv[4];
#pragma unroll
      for (int j = 0; j < 4; ++j) { a[j] = As[kk][ty * 4 + j]; bv[j] = Bs[kk][tx * 4 + j]; }
#pragma unroll
      for (int i2 = 0; i2 < 4; ++i2)
#pragma unroll
        for (int j = 0; j < 4; ++j) acc[i2][j] += a[i2] * bv[j];
    }
    __syncthreads();
  }
#pragma unroll
  for (int i2 = 0; i2 < 4; ++i2) {
    int r = r0 + ty * 4 + i2;
    float bias = bih[r] + bhh[r];
#pragma unroll
    for (int j = 0; j < 4; ++j)
      d_pre[(size_t)r * TT + (t0 + tx * 4 + j)] = acc[i2][j] + bias;
  }
}

// ---------------- encoder persistent ----------------
__global__ void __launch_bounds__(NT_ENC, 1)
enc_persist(const float* __restrict__ Whh_e) {
  __shared__ __align__(16) float shEh[H];
  const int b = blockIdx.x, tid = threadIdx.x;
  const int w = tid >> 5, lane = tid & 31;
  const int u = b * 8 + w;

  float4 wreg[4][8];
#pragma unroll
  for (int g = 0; g < 4; ++g) {
    const float4* p = (const float4*)(Whh_e + (size_t)(u + g * H) * H);
#pragma unroll
    for (int c = 0; c < 8; ++c) wreg[g][c] = __ldg(p + c * 32 + lane);
  }

  float ec = 0.f;
  for (int t = 0; t < TT; ++t) {
    float pre_g[4];
    if (lane == 0) {
#pragma unroll
      for (int g = 0; g < 4; ++g) pre_g[g] = __ldg(&d_pre[(size_t)(u + g * H) * TT + t]);
    }
    if (w == 0) poll_flags(d_fe, lane, 8u * (unsigned)t);
    __syncthreads();   // S1: all prior-step stores visible
    ((float4*)shEh)[tid] = __ldcg((const float4*)(d_EH + (size_t)t * H) + tid);
    __syncthreads();   // S2: staged

    float a[4] = {0.f, 0.f, 0.f, 0.f};
#pragma unroll
    for (int c = 0; c < 8; ++c) {
      float4 hv = ((const float4*)shEh)[c * 32 + lane];
#pragma unroll
      for (int g = 0; g < 4; ++g) a[g] += dot4(wreg[g][c], hv);
    }
#pragma unroll
    for (int g = 0; g < 4; ++g) a[g] = wredsum(a[g]);
    if (lane == 0) {
      float gi = a[0] + pre_g[0], gf = a[1] + pre_g[1];
      float gg = a[2] + pre_g[2], go = a[3] + pre_g[3];
      ec = sigf(gf) * ec + sigf(gi) * tanhf(gg);
      __stcg(&d_EH[(size_t)(t + 1) * H + u], sigf(go) * tanhf(ec));
      red_rel(&d_fe[b * FPAD]);   // per-warp release of its own store
    }
  }
}

// ---------------- decoder persistent ----------------
// smem: shWA [32][1024] = 128KB | shEh 4KB | shDh 4KB | shS
#define SMEM_DEC_FLOATS (32 * 1024 + 1024 + 1024 + 16)

__global__ void __launch_bounds__(NT_DEC, 1)
dec_persist(const float* __restrict__ Wihd, const float* __restrict__ Whhd,
            const float* __restrict__ bihd, const float* __restrict__ bhhd,
            const float* __restrict__ Wattn, const float* __restrict__ battn) {
  extern __shared__ __align__(16) float sh[];
  float* shWA = sh;                  // 32768 floats
  float* shEh = sh + 32 * 1024;      // 1024
  float* shDh = shEh + 1024;         // 1024
  float* shS  = shDh + 1024;         // 16

  const int b = blockIdx.x, tid = threadIdx.x;
  const int w = tid >> 5, lane = tid & 31;
  const int u = b * 8 + w;           // valid for w<8

  // W_A block rows -> smem: row jj = g*8+wv holds Wihd[(b*8+wv)+g*H][0:H]
  for (int i = tid; i < 32 * 256; i += NT_DEC) {
    int jj = i >> 8, c4 = i & 255;
    int g = jj >> 3, wv = jj & 7;
    ((float4*)shWA)[i] =
        __ldg((const float4*)(Wihd + ((size_t)(b * 8 + wv) + (size_t)g * H) * (2 * H)) + c4);
  }

  float4 wreg[4][8];                 // W_ih_d[:,H:] + W_hh_d rows (dh coefficients)
  float bd[4] = {0.f, 0.f, 0.f, 0.f};
  if (w < 8) {
#pragma unroll
    for (int g = 0; g < 4; ++g) {
      const int row = u + g * H;
      const float4* pA = (const float4*)(Wihd + (size_t)row * (2 * H) + H);
      const float4* pB = (const float4*)(Whhd + (size_t)row * H);
#pragma unroll
      for (int c = 0; c < 8; ++c) {
        float4 x = __ldg(pA + c * 32 + lane), y = __ldg(pB + c * 32 + lane);
        wreg[g][c] = make_float4(x.x + y.x, x.y + y.y, x.z + y.z, x.w + y.w);
      }
      bd[g] = __ldg(bihd + row) + __ldg(bhhd + row);
    }
  }
  float awreg[16];                   // warp 8: softmaxed attention weights
#pragma unroll
  for (int j = 0; j < 16; ++j) awreg[j] = 0.f;
  __syncthreads();

  float dc = 0.f;
  for (int t = 0; t < TT; ++t) {
    // warp 8: precompute static eh-half of energy while (before) polling
    float eEH = 0.f, bat = 0.f;
    if (w == 8) {
      const float4* wrE = (const float4*)(Wattn + (size_t)t * (2 * H));
      const float4* ehp = (const float4*)(d_EH + (size_t)(t + 1) * H);
#pragma unroll
      for (int c = 0; c < 8; ++c)
        eEH += dot4(__ldg(wrE + c * 32 + lane), __ldcg(ehp + c * 32 + lane));
      bat = __ldg(&battn[t]);
      poll_flags(d_fd, lane, 8u * (unsigned)t);
    }
    __syncthreads();   // S1: dh_t visible; safe to restage
    if (tid < 256) {
      ((float4*)shEh)[tid] = __ldcg((const float4*)(d_EH + (size_t)(t + 1) * H) + tid);
      ((float4*)shDh)[tid] = __ldcg((const float4*)(d_DH + (size_t)t * H) + tid);
    }
    __syncthreads();   // S2: staged

    float a[4] = {0.f, 0.f, 0.f, 0.f};
    float pa[4] = {0.f, 0.f, 0.f, 0.f};
    if (w < 8) {
#pragma unroll
      for (int c = 0; c < 8; ++c) {
        float4 dhc = ((const float4*)shDh)[c * 32 + lane];
        float4 ehc = ((const float4*)shEh)[c * 32 + lane];
#pragma unroll
        for (int g = 0; g < 4; ++g) {
          a[g]  += dot4(wreg[g][c], dhc);
          pa[g] += dot4(((const float4*)shWA)[(g * 8 + w) * 256 + c * 32 + lane], ehc);
        }
      }
#pragma unroll
      for (int g = 0; g < 4; ++g) { a[g] = wredsum(a[g]); pa[g] = wredsum(pa[g]); }
    } else {
      // dh-half of energy + register-resident softmax (eh-half already in eEH)
      const float4* wrD = (const float4*)(Wattn + (size_t)t * (2 * H)) + 256;
      float e = eEH;
#pragma unroll
      for (int c = 0; c < 8; ++c) {
        int idx = c * 32 + lane;
        e += dot4(__ldg(wrD + idx), ((const float4*)shDh)[idx]);
      }
      e = wredsum(e) + bat;
      float vals[16];
      float m = -1e30f;
#pragma unroll
      for (int j = 0; j < 16; ++j) {
        float x = (j * 32 + lane == t) ? e : awreg[j];
        vals[j] = x;
        m = fmaxf(m, x);
      }
      m = wredmax(m);
      float ssum = 0.f;
#pragma unroll
      for (int j = 0; j < 16; ++j) { vals[j] = __expf(vals[j] - m); ssum += vals[j]; }
      ssum = wredsum(ssum);
      float inv = 1.f / ssum;
#pragma unroll
      for (int j = 0; j < 16; ++j) awreg[j] = vals[j] * inv;
      if (lane == 0) shS[0] = __expf(e - m) * inv;
    }
    __syncthreads();   // S3: shS published

    if (w < 8 && lane == 0) {
      float s = shS[0];
      float gi = s * pa[0] + a[0] + bd[0];
      float gf = s * pa[1] + a[1] + bd[1];
      float gg = s * pa[2] + a[2] + bd[2];
      float go = s * pa[3] + a[3] + bd[3];
      dc = sigf(gf) * dc + sigf(gi) * tanhf(gg);
      __stcg(&d_DH[(size_t)(t + 1) * H + u], sigf(go) * tanhf(dc));
      red_rel(&d_fd[b * FPAD]);   // per-warp release of its own store
    }
  }
}

// ---------------- out[t] = Wout @ dh_{t+1} + bout ----------------
__global__ void out_final(const float* __restrict__ Wout, const float* __restrict__ bout,
                          float* __restrict__ out) {
  const int w = threadIdx.x >> 5, lane = threadIdx.x & 31;
  const int t = blockIdx.x * 8 + w;
  const float4* wo = (const float4*)Wout;
  const float4* dh = (const float4*)(d_DH + (size_t)(t + 1) * H);
  float o = 0.f;
#pragma unroll
  for (int c = 0; c < 8; ++c) o += dot4(__ldg(wo + c * 32 + lane), __ldcg(dh + c * 32 + lane));
  o = wredsum(o);
  if (lane == 0) out[t] = o + __ldg(bout);
}

// ---------------- launch ----------------
extern "C" void kernel_launch(void* const* d_in, const int* in_sizes, int n_in,
                              void* d_out, int out_size) {
  const float* input_seq = (const float*)d_in[0];
  const float* W_ih_e = (const float*)d_in[2];
  const float* W_hh_e = (const float*)d_in[3];
  const float* b_ih_e = (const float*)d_in[4];
  const float* b_hh_e = (const float*)d_in[5];
  const float* W_attn = (const float*)d_in[6];
  const float* b_attn = (const float*)d_in[7];
  const float* W_ih_d = (const float*)d_in[8];
  const float* W_hh_d = (const float*)d_in[9];
  const float* b_ih_d = (const float*)d_in[10];
  const float* b_hh_d = (const float*)d_in[11];
  const float* W_out  = (const float*)d_in[12];
  const float* b_out  = (const float*)d_in[13];
  float* out = (float*)d_out;

  const int smem_dec = SMEM_DEC_FLOATS * 4;   // ~139KB
  cudaFuncSetAttribute(dec_persist, cudaFuncAttributeMaxDynamicSharedMemorySize, smem_dec);

  init_state<<<16, 256>>>();
  gemm_pre<<<dim3(TT / BN, G / BM), 256>>>(W_ih_e, input_seq, b_ih_e, b_hh_e);
  enc_persist<<<NB, NT_ENC>>>(W_hh_e);
  dec_persist<<<NB, NT_DEC, smem_dec>>>(W_ih_d, W_hh_d, b_ih_d, b_hh_d, W_attn, b_attn);
  out_final<<<TT / 8, 256>>>(W_out, b_out, out);
}

// round 9
// speedup vs baseline: 3.0710x; 1.8761x over previous
#include <cuda_runtime.h>
#include <cstdint>

#define TT 512
#define IDIM 512
#define H 1024
#define G 4096
#define NB 128
#define NT_ENC 256
#define NT_DEC 288
#define FPAD 32    // 32 uints = one 128B line per counter
#define NGRP 32    // group counters; 4 blocks -> 8 warps*4 = 32 increments/step/counter

// ---------------- device scratch ----------------
__device__ __align__(16) float d_pre[(size_t)G * TT];       // W_ih_e@x_t + biases   [r][t]
__device__ __align__(16) float d_EH[(size_t)(TT + 1) * H];  // eh_t rows; row0 = 0
__device__ __align__(16) float d_DH[(size_t)(TT + 1) * H];  // dh_t rows; row0 = 0
__device__ unsigned d_fe[NGRP * FPAD], d_fd[NGRP * FPAD];   // padded group counters, 32/step

__device__ __forceinline__ float sigf(float x) { return 1.f / (1.f + __expf(-x)); }
__device__ __forceinline__ float dot4(float4 a, float4 b) {
  return a.x * b.x + a.y * b.y + a.z * b.z + a.w * b.w;
}
__device__ __forceinline__ float wredsum(float v) {
#pragma unroll
  for (int o = 16; o; o >>= 1) v += __shfl_xor_sync(0xffffffffu, v, o);
  return v;
}
__device__ __forceinline__ float wredmax(float v) {
#pragma unroll
  for (int o = 16; o; o >>= 1) v = fmaxf(v, __shfl_xor_sync(0xffffffffu, v, o));
  return v;
}
__device__ __forceinline__ unsigned ld_acq(const unsigned* p) {
  unsigned v;
  asm volatile("ld.acquire.gpu.global.u32 %0, [%1];" : "=r"(v) : "l"(p) : "memory");
  return v;
}
__device__ __forceinline__ void red_rel(unsigned* p) {
  unsigned one = 1u;
  asm volatile("red.release.gpu.global.add.u32 [%0], %1;" :: "l"(p), "r"(one) : "memory");
}

// one warp: each lane acquire-loads ONE group counter until all >= tgt
__device__ __forceinline__ void poll_groups(const unsigned* flags, int lane, unsigned tgt) {
  const unsigned* p = flags + (size_t)lane * FPAD;
  for (;;) {
    unsigned v = ld_acq(p);
    if (__all_sync(0xffffffffu, v >= tgt)) break;
    __nanosleep(32);
  }
}

// ---------------- init ----------------
__global__ void init_state() {
  int i = blockIdx.x * blockDim.x + threadIdx.x;
  if (i < H) { d_EH[i] = 0.f; d_DH[i] = 0.f; }
  if (i < NGRP * FPAD) { d_fe[i] = 0u; d_fd[i] = 0u; }
}

// ---------------- R2-proven GEMM: d_pre[r][t] = W_ih_e@x_t + b_ih_e + b_hh_e ----------------
#define BM 64
#define BN 64
#define BK 32
__global__ void __launch_bounds__(256) gemm_pre(const float* __restrict__ A,
                                                const float* __restrict__ B,
                                                const float* __restrict__ bih,
                                                const float* __restrict__ bhh) {
  __shared__ float As[BK][BM + 1];
  __shared__ float Bs[BK][BN + 1];
  int tid = threadIdx.x;
  int r0 = blockIdx.y * BM;
  int t0 = blockIdx.x * BN;
  int tx = tid & 15, ty = tid >> 4;
  float acc[4][4] = {};
  for (int k0 = 0; k0 < IDIM; k0 += BK) {
#pragma unroll
    for (int i = 0; i < 8; ++i) {
      int lin = tid + i * 256;
      int m = lin >> 5, kk = lin & 31;
      As[kk][m] = A[(size_t)(r0 + m) * IDIM + k0 + kk];
      Bs[kk][m] = B[(size_t)(t0 + m) * IDIM + k0 + kk];
    }
    __syncthreads();
#pragma unroll
    for (int kk = 0; kk < BK; ++kk) {
      float a[4], bv[4];
#pragma unroll
      for (int j = 0; j < 4; ++j) { a[j] = As[kk][ty * 4 + j]; bv[j] = Bs[kk][tx * 4 + j]; }
#pragma unroll
      for (int i2 = 0; i2 < 4; ++i2)
#pragma unroll
        for (int j = 0; j < 4; ++j) acc[i2][j] += a[i2] * bv[j];
    }
    __syncthreads();
  }
#pragma unroll
  for (int i2 = 0; i2 < 4; ++i2) {
    int r = r0 + ty * 4 + i2;
    float bias = bih[r] + bhh[r];
#pragma unroll
    for (int j = 0; j < 4; ++j)
      d_pre[(size_t)r * TT + (t0 + tx * 4 + j)] = acc[i2][j] + bias;
  }
}

// ---------------- encoder persistent ----------------
__global__ void __launch_bounds__(NT_ENC, 1)
enc_persist(const float* __restrict__ Whh_e) {
  __shared__ __align__(16) float shEh[H];
  const int b = blockIdx.x, tid = threadIdx.x;
  const int w = tid >> 5, lane = tid & 31;
  const int u = b * 8 + w;
  unsigned* myflag = &d_fe[(b >> 2) * FPAD];

  float4 wreg[4][8];
#pragma unroll
  for (int g = 0; g < 4; ++g) {
    const float4* p = (const float4*)(Whh_e + (size_t)(u + g * H) * H);
#pragma unroll
    for (int c = 0; c < 8; ++c) wreg[g][c] = __ldg(p + c * 32 + lane);
  }

  float ec = 0.f;
  for (int t = 0; t < TT; ++t) {
    float pre_g[4];
    if (lane == 0) {
#pragma unroll
      for (int g = 0; g < 4; ++g) pre_g[g] = __ldg(&d_pre[(size_t)(u + g * H) * TT + t]);
    }
    if (w == 0) poll_groups(d_fe, lane, 32u * (unsigned)t);
    __syncthreads();   // S1: all prior-step stores visible
    ((float4*)shEh)[tid] = __ldcg((const float4*)(d_EH + (size_t)t * H) + tid);
    __syncthreads();   // S2: staged

    float a[4] = {0.f, 0.f, 0.f, 0.f};
#pragma unroll
    for (int c = 0; c < 8; ++c) {
      float4 hv = ((const float4*)shEh)[c * 32 + lane];
#pragma unroll
      for (int g = 0; g < 4; ++g) a[g] += dot4(wreg[g][c], hv);
    }
#pragma unroll
    for (int g = 0; g < 4; ++g) a[g] = wredsum(a[g]);
    if (lane == 0) {
      float gi = a[0] + pre_g[0], gf = a[1] + pre_g[1];
      float gg = a[2] + pre_g[2], go = a[3] + pre_g[3];
      ec = sigf(gf) * ec + sigf(gi) * tanhf(gg);
      __stcg(&d_EH[(size_t)(t + 1) * H + u], sigf(go) * tanhf(ec));
      red_rel(myflag);   // per-warp release of its own store
    }
  }
}

// ---------------- decoder persistent ----------------
// smem: shWA [32][1024] = 128KB | shEh 4KB | shDh 4KB | shS
#define SMEM_DEC_FLOATS (32 * 1024 + 1024 + 1024 + 16)

__global__ void __launch_bounds__(NT_DEC, 1)
dec_persist(const float* __restrict__ Wihd, const float* __restrict__ Whhd,
            const float* __restrict__ bihd, const float* __restrict__ bhhd,
            const float* __restrict__ Wattn, const float* __restrict__ battn) {
  extern __shared__ __align__(16) float sh[];
  float* shWA = sh;                  // 32768 floats
  float* shEh = sh + 32 * 1024;      // 1024
  float* shDh = shEh + 1024;         // 1024
  float* shS  = shDh + 1024;         // 16

  const int b = blockIdx.x, tid = threadIdx.x;
  const int w = tid >> 5, lane = tid & 31;
  const int u = b * 8 + w;           // valid for w<8
  unsigned* myflag = &d_fd[(b >> 2) * FPAD];

  // W_A block rows -> smem: row jj = g*8+wv holds Wihd[(b*8+wv)+g*H][0:H]
  for (int i = tid; i < 32 * 256; i += NT_DEC) {
    int jj = i >> 8, c4 = i & 255;
    int g = jj >> 3, wv = jj & 7;
    ((float4*)shWA)[i] =
        __ldg((const float4*)(Wihd + ((size_t)(b * 8 + wv) + (size_t)g * H) * (2 * H)) + c4);
  }

  float4 wreg[4][8];                 // W_ih_d[:,H:] + W_hh_d rows (dh coefficients)
  float bd[4] = {0.f, 0.f, 0.f, 0.f};
  if (w < 8) {
#pragma unroll
    for (int g = 0; g < 4; ++g) {
      const int row = u + g * H;
      const float4* pA = (const float4*)(Wihd + (size_t)row * (2 * H) + H);
      const float4* pB = (const float4*)(Whhd + (size_t)row * H);
#pragma unroll
      for (int c = 0; c < 8; ++c) {
        float4 x = __ldg(pA + c * 32 + lane), y = __ldg(pB + c * 32 + lane);
        wreg[g][c] = make_float4(x.x + y.x, x.y + y.y, x.z + y.z, x.w + y.w);
      }
      bd[g] = __ldg(bihd + row) + __ldg(bhhd + row);
    }
  }
  float awreg[16];                   // warp 8: softmaxed attention weights
#pragma unroll
  for (int j = 0; j < 16; ++j) awreg[j] = 0.f;
  __syncthreads();

  float dc = 0.f;
  for (int t = 0; t < TT; ++t) {
    // warp 8: precompute static eh-half of energy before polling
    float eEH = 0.f, bat = 0.f;
    if (w == 8) {
      const float4* wrE = (const float4*)(Wattn + (size_t)t * (2 * H));
      const float4* ehp = (const float4*)(d_EH + (size_t)(t + 1) * H);
#pragma unroll
      for (int c = 0; c < 8; ++c)
        eEH += dot4(__ldg(wrE + c * 32 + lane), __ldcg(ehp + c * 32 + lane));
      bat = __ldg(&battn[t]);
      poll_groups(d_fd, lane, 32u * (unsigned)t);
    }
    __syncthreads();   // S1: dh_t visible; safe to restage
    if (tid < 256) {
      ((float4*)shEh)[tid] = __ldcg((const float4*)(d_EH + (size_t)(t + 1) * H) + tid);
      ((float4*)shDh)[tid] = __ldcg((const float4*)(d_DH + (size_t)t * H) + tid);
    }
    __syncthreads();   // S2: staged

    float a[4] = {0.f, 0.f, 0.f, 0.f};
    float pa[4] = {0.f, 0.f, 0.f, 0.f};
    if (w < 8) {
#pragma unroll
      for (int c = 0; c < 8; ++c) {
        float4 dhc = ((const float4*)shDh)[c * 32 + lane];
        float4 ehc = ((const float4*)shEh)[c * 32 + lane];
#pragma unroll
        for (int g = 0; g < 4; ++g) {
          a[g]  += dot4(wreg[g][c], dhc);
          pa[g] += dot4(((const float4*)shWA)[(g * 8 + w) * 256 + c * 32 + lane], ehc);
        }
      }
#pragma unroll
      for (int g = 0; g < 4; ++g) { a[g] = wredsum(a[g]); pa[g] = wredsum(pa[g]); }
    } else {
      // dh-half of energy + register-resident softmax (eh-half already in eEH)
      const float4* wrD = (const float4*)(Wattn + (size_t)t * (2 * H)) + 256;
      float e = eEH;
#pragma unroll
      for (int c = 0; c < 8; ++c) {
        int idx = c * 32 + lane;
        e += dot4(__ldg(wrD + idx), ((const float4*)shDh)[idx]);
      }
      e = wredsum(e) + bat;
      float vals[16];
      float m = -1e30f;
#pragma unroll
      for (int j = 0; j < 16; ++j) {
        float x = (j * 32 + lane == t) ? e : awreg[j];
        vals[j] = x;
        m = fmaxf(m, x);
      }
      m = wredmax(m);
      float ssum = 0.f;
#pragma unroll
      for (int j = 0; j < 16; ++j) { vals[j] = __expf(vals[j] - m); ssum += vals[j]; }
      ssum = wredsum(ssum);
      float inv = 1.f / ssum;
#pragma unroll
      for (int j = 0; j < 16; ++j) awreg[j] = vals[j] * inv;
      if (lane == 0) shS[0] = __expf(e - m) * inv;
    }
    __syncthreads();   // S3: shS published

    if (w < 8 && lane == 0) {
      float s = shS[0];
      float gi = s * pa[0] + a[0] + bd[0];
      float gf = s * pa[1] + a[1] + bd[1];
      float gg = s * pa[2] + a[2] + bd[2];
      float go = s * pa[3] + a[3] + bd[3];
      dc = sigf(gf) * dc + sigf(gi) * tanhf(gg);
      __stcg(&d_DH[(size_t)(t + 1) * H + u], sigf(go) * tanhf(dc));
      red_rel(myflag);   // per-warp release of its own store
    }
  }
}

// ---------------- out[t] = Wout @ dh_{t+1} + bout ----------------
__global__ void out_final(const float* __restrict__ Wout, const float* __restrict__ bout,
                          float* __restrict__ out) {
  const int w = threadIdx.x >> 5, lane = threadIdx.x & 31;
  const int t = blockIdx.x * 8 + w;
  const float4* wo = (const float4*)Wout;
  const float4* dh = (const float4*)(d_DH + (size_t)(t + 1) * H);
  float o = 0.f;
#pragma unroll
  for (int c = 0; c < 8; ++c) o += dot4(__ldg(wo + c * 32 + lane), __ldcg(dh + c * 32 + lane));
  o = wredsum(o);
  if (lane == 0) out[t] = o + __ldg(bout);
}

// ---------------- launch ----------------
extern "C" void kernel_launch(void* const* d_in, const int* in_sizes, int n_in,
                              void* d_out, int out_size) {
  const float* input_seq = (const float*)d_in[0];
  const float* W_ih_e = (const float*)d_in[2];
  const float* W_hh_e = (const float*)d_in[3];
  const float* b_ih_e = (const float*)d_in[4];
  const float* b_hh_e = (const float*)d_in[5];
  const float* W_attn = (const float*)d_in[6];
  const float* b_attn = (const float*)d_in[7];
  const float* W_ih_d = (const float*)d_in[8];
  const float* W_hh_d = (const float*)d_in[9];
  const float* b_ih_d = (const float*)d_in[10];
  const float* b_hh_d = (const float*)d_in[11];
  const float* W_out  = (const float*)d_in[12];
  const float* b_out  = (const float*)d_in[13];
  float* out = (float*)d_out;

  const int smem_dec = SMEM_DEC_FLOATS * 4;   // ~139KB
  cudaFuncSetAttribute(dec_persist, cudaFuncAttributeMaxDynamicSharedMemorySize, smem_dec);

  init_state<<<8, 256>>>();
  gemm_pre<<<dim3(TT / BN, G / BM), 256>>>(W_ih_e, input_seq, b_ih_e, b_hh_e);
  enc_persist<<<NB, NT_ENC>>>(W_hh_e);
  dec_persist<<<NB, NT_DEC, smem_dec>>>(W_ih_d, W_hh_d, b_ih_d, b_hh_d, W_attn, b_attn);
  out_final<<<TT / 8, 256>>>(W_out, b_out, out);
}